// round 2
// baseline (speedup 1.0000x reference)
#include <cuda_runtime.h>
#include <cstdint>

// ---------------------------------------------------------------------------
// Radon transform, 180 angles, 512x512, batch 2 — round 2.
//
// Evidence from R1 ncu: L1tex-bound (75.6%), DRAM 0.3%. The cost is L1
// wavefronts = distinct 128B lines per warp gather = rows spanned by lanes.
//
// Changes:
//  1. Row-pair interleaved layout: each lattice cell (x,y) stores 8 floats
//     (both batches x {x,x+1} x {y,y+1}) in 32 contiguous bytes. The two
//     LDG.128 per bilinear sample hit the SAME cache line.
//  2. Two orientations (normal + transposed). Per angle pick the one where
//     the memory-fast coordinate varies fastest across lanes: row-perp slope
//     becomes min(|sin|,|cos|) <= 0.707 instead of |sin|.
//  3. r-loop split in 2 (gridDim.z) + atomicAdd epilogue for occupancy.
// ---------------------------------------------------------------------------

#define W    512
#define NT   180
#define PS   520                  // entry row stride (x), 520*32B = 128B-aligned
#define PH   516                  // entry rows (y); max used index 514
#define NENT (PS * PH)

__device__ float4 g_padA[2 * NENT];   // normal orientation, 2 float4 per cell
__device__ float4 g_padB[2 * NENT];   // transposed orientation

typedef unsigned long long u64;

__device__ __forceinline__ u64 pk2(float lo, float hi) {
    u64 r; asm("mov.b64 %0, {%1, %2};" : "=l"(r) : "f"(lo), "f"(hi)); return r;
}
__device__ __forceinline__ void unpk2(u64 v, float& lo, float& hi) {
    asm("mov.b64 {%0, %1}, %2;" : "=f"(lo), "=f"(hi) : "l"(v));
}
__device__ __forceinline__ u64 ffma2(u64 a, u64 b, u64 c) {
    u64 d; asm("fma.rn.f32x2 %0, %1, %2, %3;" : "=l"(d) : "l"(a), "l"(b), "l"(c)); return d;
}
__device__ __forceinline__ u64 fadd2(u64 a, u64 b) {
    u64 d; asm("add.rn.f32x2 %0, %1, %2;" : "=l"(d) : "l"(a), "l"(b)); return d;
}

// ---- build both padded row-pair arrays --------------------------------------
// blockIdx.y = orientation (0 = normal, 1 = transposed).
__global__ void build_pad(const float* __restrict__ x) {
    int idx = blockIdx.x * blockDim.x + threadIdx.x;
    if (idx >= NENT) return;
    int tr = blockIdx.y;
    int ky = idx / PS;
    int kx = idx - ky * PS;
    int y  = ky - 2;
    int xx = kx - 2;

    // fetch img[b][r][c] with zero padding; transposed swaps (r,c)
    auto val = [&](int b, int r, int c) -> float {
        if (tr) { int t2 = r; r = c; c = t2; }
        if ((unsigned)r < W && (unsigned)c < W)
            return x[b * (W * W) + r * W + c];
        return 0.0f;
    };

    float4 e0 = make_float4(val(0, y,     xx), val(1, y,     xx),
                            val(0, y,     xx + 1), val(1, y,     xx + 1));
    float4 e1 = make_float4(val(0, y + 1, xx), val(1, y + 1, xx),
                            val(0, y + 1, xx + 1), val(1, y + 1, xx + 1));
    float4* dst = tr ? g_padB : g_padA;
    dst[2 * idx]     = e0;
    dst[2 * idx + 1] = e1;
}

__global__ void zero_out(float* __restrict__ out, int n) {
    int i = blockIdx.x * blockDim.x + threadIdx.x;
    if (i < n) out[i] = 0.0f;
}

// ---- main kernel ------------------------------------------------------------
__global__ __launch_bounds__(128) void radon_kernel(float* __restrict__ out) {
    int c    = blockIdx.x * 128 + threadIdx.x;   // detector column 0..511
    int t    = blockIdx.y;                       // angle 0..179
    int half = blockIdx.z;                       // r-range half

    float th = (float)t * 0.017453292519943295f;
    float s  = sinf(th);                         // >= 0 for t in [0,180)
    float ct = cosf(th);

    float base_c = (float)(2 * c + 1) * (1.0f / 512.0f) - 1.0f;
    float ix0 = fmaf(-255.5f, s,  fmaf( 256.0f * ct, base_c, 255.5f));
    float iy0 = fmaf(-255.5f, ct, fmaf(-256.0f * s,  base_c, 255.5f));

    // clip r to where (ix,iy) in [-1,512]^2 ; +-1 step slop absorbed by padding
    float sx  = fmaxf(s, 1e-8f);
    float sy  = (fabsf(ct) < 1e-8f) ? ((ct < 0.f) ? -1e-8f : 1e-8f) : ct;
    float ivx = 1.0f / sx;
    float ivy = 1.0f / sy;
    float tx1 = (-1.0f  - ix0) * ivx;
    float tx2 = (512.0f - ix0) * ivx;
    float ty1 = (-1.0f  - iy0) * ivy;
    float ty2 = (512.0f - iy0) * ivy;
    float rminf = fmaxf(fmaxf(fminf(tx1, tx2), fminf(ty1, ty2)), 0.0f);
    float rmaxf = fminf(fminf(fmaxf(tx1, tx2), fmaxf(ty1, ty2)), 511.0f);
    rminf = fminf(rminf, 1024.0f);
    rmaxf = fmaxf(rmaxf, -2.0f);
    int rlo = (int)floorf(rminf);
    int rhi = (int)ceilf(rmaxf);

    // orientation select (uniform per block: t is per-block)
    bool tr = s > fabsf(ct);
    float xc0, yc0, dxs, dys;
    const float4* __restrict__ base;
    if (!tr) { xc0 = ix0 + 2.0f; dxs = s;  yc0 = iy0 + 2.0f; dys = ct; base = g_padA; }
    else     { xc0 = iy0 + 2.0f; dxs = ct; yc0 = ix0 + 2.0f; dys = s;  base = g_padB; }

    // split r-range across gridDim.z = 2
    int mid = (rlo + rhi) >> 1;
    int ra = half ? (mid + 1) : rlo;
    int rb = half ? rhi       : mid;

    const u64 M1 = pk2(-1.0f, -1.0f);
    u64 acc = pk2(0.0f, 0.0f);

#pragma unroll 4
    for (int r = ra; r <= rb; ++r) {
        float rf = (float)r;
        float px = fmaf(rf, dxs, xc0);
        float py = fmaf(rf, dys, yc0);
        int   x0 = (int)px;                      // coords >= 0: trunc == floor
        int   y0 = (int)py;
        float fx = px - (float)x0;
        float fy = py - (float)y0;

        int o = (y0 * PS + x0) * 2;
        float4 va = __ldg(base + o);             // (v00.b0, v00.b1, v01.b0, v01.b1)
        float4 vb = __ldg(base + o + 1);         // (v10.b0, v10.b1, v11.b0, v11.b1)

        u64 v00 = pk2(va.x, va.y);
        u64 v01 = pk2(va.z, va.w);
        u64 v10 = pk2(vb.x, vb.y);
        u64 v11 = pk2(vb.z, vb.w);
        u64 fxp = pk2(fx, fx);
        u64 fyp = pk2(fy, fy);

        u64 d0 = ffma2(v00, M1, v01);            // v01 - v00
        u64 l0 = ffma2(fxp, d0, v00);
        u64 d1 = ffma2(v10, M1, v11);            // v11 - v10
        u64 l1 = ffma2(fxp, d1, v10);
        u64 dl = ffma2(l0, M1, l1);              // l1 - l0
        u64 vv = ffma2(fyp, dl, l0);
        acc = fadd2(acc, vv);
    }

    float a0, a1;
    unpk2(acc, a0, a1);
    const float inv = 1.0f / 512.0f;
    int o0 = c * NT + t;
    atomicAdd(&out[o0],           a0 * inv);     // batch 0
    atomicAdd(&out[W * NT + o0],  a1 * inv);     // batch 1
}

extern "C" void kernel_launch(void* const* d_in, const int* in_sizes, int n_in,
                              void* d_out, int out_size) {
    const float* x = (const float*)d_in[0];
    float* out = (float*)d_out;

    dim3 bgrid((NENT + 255) / 256, 2);
    build_pad<<<bgrid, 256>>>(x);

    zero_out<<<(out_size + 255) / 256, 256>>>(out, out_size);

    dim3 grid(W / 128, NT, 2);
    radon_kernel<<<grid, 128>>>(out);
}

// round 4
// speedup vs baseline: 1.4288x; 1.4288x over previous
#include <cuda_runtime.h>
#include <cstdint>

// ---------------------------------------------------------------------------
// Radon transform, 180 angles, 512x512, batch 2 — round 3 resubmit (infra
// failure last round; same experiment so the prediction stays testable).
//
// R1 evidence: L1tex-bound (75.6%), grid-limited occupancy (26%), issue 18.6%.
// R2 lesson: row-pair duplication didn't cut wavefronts; heavy build regressed.
//
// Changes vs R1 (158us):
//  1. Keep R1's 16B cell layout: pad[y][x] = (b0[y][x], b1[y][x],
//     b0[y][x+1], b1[y][x+1]); one LDG.128 per row per sample, 2 requests.
//  2. TWO orientations (normal + transposed). Per angle, pick the one where
//     the across-lane row slope is min(|sin|,|cos|) <= 0.707: fewer distinct
//     image rows per warp request -> ~0.6x L1 wavefronts on average.
//  3. Row stride 520 cells (520*16B multiple of 128B).
//  4. r-range split in 2 (gridDim.z) for 1440 blocks (~39 warps/SM) to hide
//     L1 latency; zero-init + atomicAdd epilogue (2 atomics/thread, cheap).
// ---------------------------------------------------------------------------

#define W    512
#define NT   180
#define PW   520                 // cell row stride; 520*16B multiple of 128B
#define PH   517                 // rows used: index up to 516
#define NPIX (PW * PH)

__device__ float4 g_padA[NPIX];  // normal orientation
__device__ float4 g_padB[NPIX];  // transposed orientation

typedef unsigned long long u64;

__device__ __forceinline__ u64 pk2(float lo, float hi) {
    u64 r; asm("mov.b64 %0, {%1, %2};" : "=l"(r) : "f"(lo), "f"(hi)); return r;
}
__device__ __forceinline__ void unpk2(u64 v, float& lo, float& hi) {
    asm("mov.b64 {%0, %1}, %2;" : "=f"(lo), "=f"(hi) : "l"(v));
}
__device__ __forceinline__ u64 ffma2(u64 a, u64 b, u64 c) {
    u64 d; asm("fma.rn.f32x2 %0, %1, %2, %3;" : "=l"(d) : "l"(a), "l"(b), "l"(c)); return d;
}
__device__ __forceinline__ u64 fadd2(u64 a, u64 b) {
    u64 d; asm("add.rn.f32x2 %0, %1, %2;" : "=l"(d) : "l"(a), "l"(b)); return d;
}

// ---- build both padded arrays (blockIdx.y = orientation) --------------------
__global__ void build_pad(const float* __restrict__ x) {
    int idx = blockIdx.x * blockDim.x + threadIdx.x;
    if (idx >= NPIX) return;
    int tr = blockIdx.y;
    int ky = idx / PW;
    int kx = idx - ky * PW;
    int y  = ky - 2;
    int x0 = kx - 2;

    auto val = [&](int b, int r, int c) -> float {
        if (tr) { int t2 = r; r = c; c = t2; }
        if ((unsigned)r < W && (unsigned)c < W)
            return x[b * (W * W) + r * W + c];
        return 0.0f;
    };

    float4 e = make_float4(val(0, y, x0),     val(1, y, x0),
                           val(0, y, x0 + 1), val(1, y, x0 + 1));
    (tr ? g_padB : g_padA)[idx] = e;
}

__global__ void zero_out(float* __restrict__ out, int n) {
    int i = blockIdx.x * blockDim.x + threadIdx.x;
    int stride = gridDim.x * blockDim.x;
    for (; i < n; i += stride) out[i] = 0.0f;
}

// ---- main kernel ------------------------------------------------------------
__global__ __launch_bounds__(128) void radon_kernel(float* __restrict__ out) {
    int c    = blockIdx.x * 128 + threadIdx.x;   // detector column 0..511
    int t    = blockIdx.y;                       // angle 0..179
    int half = blockIdx.z;                       // r-range half

    float th = (float)t * 0.017453292519943295f;
    float s  = sinf(th);                         // >= 0 for t in [0,180)
    float ct = cosf(th);

    float base_c = (float)(2 * c + 1) * (1.0f / 512.0f) - 1.0f;
    float ix0 = fmaf(-255.5f, s,  fmaf( 256.0f * ct, base_c, 255.5f));
    float iy0 = fmaf(-255.5f, ct, fmaf(-256.0f * s,  base_c, 255.5f));

    // clip r to where (ix,iy) in [-1,512]^2 ; +-1 step slop absorbed by pad
    float sx  = fmaxf(s, 1e-8f);
    float sy  = (fabsf(ct) < 1e-8f) ? ((ct < 0.f) ? -1e-8f : 1e-8f) : ct;
    float ivx = 1.0f / sx;
    float ivy = 1.0f / sy;
    float tx1 = (-1.0f  - ix0) * ivx;
    float tx2 = (512.0f - ix0) * ivx;
    float ty1 = (-1.0f  - iy0) * ivy;
    float ty2 = (512.0f - iy0) * ivy;
    float rminf = fmaxf(fmaxf(fminf(tx1, tx2), fminf(ty1, ty2)), 0.0f);
    float rmaxf = fminf(fminf(fmaxf(tx1, tx2), fmaxf(ty1, ty2)), 511.0f);
    rminf = fminf(rminf, 1024.0f);
    rmaxf = fmaxf(rmaxf, -2.0f);
    int rlo = (int)floorf(rminf);
    int rhi = (int)ceilf(rmaxf);

    // orientation select (uniform per block): minimize across-lane row slope.
    // normal:     y-slope across lanes = -s   (use when s <= |ct|)
    // transposed: y-slope across lanes =  ct  (use when s >  |ct|)
    bool tr = s > fabsf(ct);
    float xc0, yc0, dxs, dys;
    const float4* __restrict__ base;
    if (!tr) { xc0 = ix0 + 2.0f; dxs = s;  yc0 = iy0 + 2.0f; dys = ct; base = g_padA; }
    else     { xc0 = iy0 + 2.0f; dxs = ct; yc0 = ix0 + 2.0f; dys = s;  base = g_padB; }

    // split r-range across gridDim.z = 2
    int mid = (rlo + rhi) >> 1;
    int ra = half ? (mid + 1) : rlo;
    int rb = half ? rhi       : mid;

    const u64 M1 = pk2(-1.0f, -1.0f);
    u64 acc = pk2(0.0f, 0.0f);

#pragma unroll 4
    for (int r = ra; r <= rb; ++r) {
        float rf = (float)r;
        float px = fmaf(rf, dxs, xc0);
        float py = fmaf(rf, dys, yc0);
        int   x0 = (int)px;                      // coords >= 0: trunc == floor
        int   y0 = (int)py;
        float fx = px - (float)x0;
        float fy = py - (float)y0;

        int o = y0 * PW + x0;
        float4 va = __ldg(base + o);             // row y0:   b0@x, b1@x, b0@x+1, b1@x+1
        float4 vb = __ldg(base + o + PW);        // row y0+1

        u64 v00 = pk2(va.x, va.y);
        u64 v01 = pk2(va.z, va.w);
        u64 v10 = pk2(vb.x, vb.y);
        u64 v11 = pk2(vb.z, vb.w);
        u64 fxp = pk2(fx, fx);
        u64 fyp = pk2(fy, fy);

        u64 d0 = ffma2(v00, M1, v01);            // v01 - v00
        u64 l0 = ffma2(fxp, d0, v00);
        u64 d1 = ffma2(v10, M1, v11);            // v11 - v10
        u64 l1 = ffma2(fxp, d1, v10);
        u64 dl = ffma2(l0, M1, l1);              // l1 - l0
        u64 vv = ffma2(fyp, dl, l0);
        acc = fadd2(acc, vv);
    }

    float a0, a1;
    unpk2(acc, a0, a1);
    const float inv = 1.0f / 512.0f;
    int o0 = c * NT + t;
    atomicAdd(&out[o0],          a0 * inv);      // batch 0
    atomicAdd(&out[W * NT + o0], a1 * inv);      // batch 1
}

extern "C" void kernel_launch(void* const* d_in, const int* in_sizes, int n_in,
                              void* d_out, int out_size) {
    const float* x = (const float*)d_in[0];
    float* out = (float*)d_out;

    dim3 bgrid((NPIX + 255) / 256, 2);
    build_pad<<<bgrid, 256>>>(x);

    zero_out<<<(out_size + 255) / 256, 256>>>(out, out_size);

    dim3 grid(W / 128, NT, 2);
    radon_kernel<<<grid, 128>>>(out);
}